// round 1
// baseline (speedup 1.0000x reference)
#include <cuda_runtime.h>

// Problem constants
#define B_TOT  2
#define E_TOT  2048
#define N1_TOT 96
#define K_TOT  32
#define CIN    64
#define CB     32
#define COUT   64
#define G_TOT  4
#define F_TOT  160   // 2*CIN + CB
#define NEG_SLOPE 0.01f

// Wbar = mean_g W_eq[g]  (F x COUT), computed once per launch by prep kernel.
__device__ float g_Wbar[F_TOT * COUT];

// ---------------------------------------------------------------------------
// Prep: compute Wbar and zero the output (d_out is poisoned by harness).
// ---------------------------------------------------------------------------
__global__ void prep_kernel(const float* __restrict__ W_eq, float* __restrict__ out) {
    int i = blockIdx.x * blockDim.x + threadIdx.x;
    if (i < F_TOT * COUT) {
        float s = W_eq[i]
                + W_eq[1 * F_TOT * COUT + i]
                + W_eq[2 * F_TOT * COUT + i]
                + W_eq[3 * F_TOT * COUT + i];
        g_Wbar[i] = 0.25f * s;
    }
    if (i < B_TOT * K_TOT * COUT) out[i] = 0.0f;
}

// ---------------------------------------------------------------------------
// Main: per edge-instance (b,e):
//   v(160) = [sites1[b,idx1[e]], sites2[b,idx2[e]], bonds[b,e]]
//   lat    = leaky_relu(v @ Wbar + b_eq)
//   att    = sigmoid(lat . W_att + b_att)
//   atomicAdd(out[b, idx2[e], :], att * lat)
//
// Layout: 128 blocks x 256 threads (8 warps). Each warp handles 4 edge
// instances jointly (reuses each Wbar shared load across 4 edges).
// Thread t owns output pair {2t, 2t+1}; accumulation via packed fma.rn.f32x2.
// ---------------------------------------------------------------------------
__global__ void __launch_bounds__(256, 1) main_kernel(
    const float* __restrict__ sites1,
    const float* __restrict__ sites2,
    const float* __restrict__ bonds,
    const float* __restrict__ b_eq,
    const float* __restrict__ W_att,
    const float* __restrict__ b_att,
    const int*   __restrict__ idx1,
    const int*   __restrict__ idx2,
    float* __restrict__ out)
{
    extern __shared__ float smem[];
    float* Wsh = smem;                                             // F_TOT*COUT floats (40960 B)
    unsigned long long* vsh =
        (unsigned long long*)(smem + F_TOT * COUT);                // [8 warps][4 edges][F_TOT] (40960 B)

    const int tid  = threadIdx.x;
    const int lane = tid & 31;
    const int w    = tid >> 5;

    // Stage Wbar into shared (coalesced from L2-resident g_Wbar).
    #pragma unroll
    for (int i = tid; i < F_TOT * COUT; i += 256) Wsh[i] = g_Wbar[i];
    __syncthreads();

    // Per-thread constants for the output pair {2*lane, 2*lane+1}.
    const float be0 = b_eq[2 * lane];
    const float be1 = b_eq[2 * lane + 1];
    const float wa0 = W_att[2 * lane];
    const float wa1 = W_att[2 * lane + 1];
    const float ba  = b_att[0];

    unsigned long long* vw = vsh + (size_t)w * 4 * F_TOT;

    // This warp's 4 edge instances.
    const int ebase = blockIdx.x * 32 + w * 4;
    int bb[4], ee[4], k2[4];

    #pragma unroll
    for (int j = 0; j < 4; j++) {
        const int ei = ebase + j;            // 0..4095
        const int b  = ei >> 11;             // /E_TOT
        const int e  = ei & (E_TOT - 1);
        bb[j] = b; ee[j] = e;
        const int i1 = idx1[e];
        const int i2 = idx2[e];
        k2[j] = i2;
        // Stage v duplicated into both f32x2 halves: vsh[f] = {v,v}.
        #pragma unroll
        for (int m = 0; m < 5; m++) {
            const int f = lane + 32 * m;     // 0..159
            float v;
            if (f < CIN)            v = sites1[(b * N1_TOT + i1) * CIN + f];
            else if (f < 2 * CIN)   v = sites2[(b * K_TOT  + i2) * CIN + (f - CIN)];
            else                    v = bonds [(b * E_TOT  + e ) * CB  + (f - 2 * CIN)];
            const unsigned u = __float_as_uint(v);
            vw[j * F_TOT + f] = ((unsigned long long)u << 32) | (unsigned long long)u;
        }
    }
    __syncwarp();

    // Packed accumulators: low half -> o=2*lane, high half -> o=2*lane+1.
    unsigned long long acc0 = 0ull, acc1 = 0ull, acc2 = 0ull, acc3 = 0ull;

    #pragma unroll 8
    for (int f = 0; f < F_TOT; f++) {
        const unsigned long long wp =
            *(const unsigned long long*)(&Wsh[f * COUT + 2 * lane]);   // {W[f][2t], W[f][2t+1]}
        const unsigned long long v0 = vw[0 * F_TOT + f];
        const unsigned long long v1 = vw[1 * F_TOT + f];
        const unsigned long long v2 = vw[2 * F_TOT + f];
        const unsigned long long v3 = vw[3 * F_TOT + f];
        asm("fma.rn.f32x2 %0, %1, %2, %0;" : "+l"(acc0) : "l"(v0), "l"(wp));
        asm("fma.rn.f32x2 %0, %1, %2, %0;" : "+l"(acc1) : "l"(v1), "l"(wp));
        asm("fma.rn.f32x2 %0, %1, %2, %0;" : "+l"(acc2) : "l"(v2), "l"(wp));
        asm("fma.rn.f32x2 %0, %1, %2, %0;" : "+l"(acc3) : "l"(v3), "l"(wp));
    }

    unsigned long long accs[4] = {acc0, acc1, acc2, acc3};

    #pragma unroll
    for (int j = 0; j < 4; j++) {
        float y0 = __uint_as_float((unsigned)(accs[j] & 0xffffffffull));
        float y1 = __uint_as_float((unsigned)(accs[j] >> 32));
        y0 += be0; y1 += be1;
        y0 = (y0 > 0.0f) ? y0 : NEG_SLOPE * y0;
        y1 = (y1 > 0.0f) ? y1 : NEG_SLOPE * y1;

        // Attention: warp-reduce lat . W_att over all 64 outputs.
        float p = y0 * wa0 + y1 * wa1;
        #pragma unroll
        for (int s = 16; s > 0; s >>= 1)
            p += __shfl_xor_sync(0xffffffffu, p, s);
        const float att = 1.0f / (1.0f + __expf(-(p + ba)));

        float* dst = out + ((size_t)(bb[j] * K_TOT + k2[j])) * COUT + 2 * lane;
        atomicAdd(dst,     y0 * att);
        atomicAdd(dst + 1, y1 * att);
    }
}

// ---------------------------------------------------------------------------
extern "C" void kernel_launch(void* const* d_in, const int* in_sizes, int n_in,
                              void* d_out, int out_size)
{
    const float* sites1 = (const float*)d_in[0];
    const float* sites2 = (const float*)d_in[1];
    const float* bonds  = (const float*)d_in[2];
    const float* W_eq   = (const float*)d_in[3];
    const float* b_eq   = (const float*)d_in[4];
    const float* W_att  = (const float*)d_in[5];
    const float* b_att  = (const float*)d_in[6];
    // d_in[7] = idx2_oh (unused — collapsed analytically)
    const int*   idx1   = (const int*)d_in[8];
    const int*   idx2   = (const int*)d_in[9];
    // d_in[10], d_in[11] = perms1/perms2 (unused — permutations cancel)
    float* out = (float*)d_out;

    const int smem_bytes = F_TOT * COUT * 4            // Wsh
                         + 8 * 4 * F_TOT * 8;          // vsh (dup f32x2)
    cudaFuncSetAttribute(main_kernel,
                         cudaFuncAttributeMaxDynamicSharedMemorySize, smem_bytes);

    // prep: Wbar (10240 elems) + zero out (4096 elems)
    prep_kernel<<<40, 256>>>(W_eq, out);

    // main: 4096 edge instances / (8 warps * 4 edges) = 128 blocks
    main_kernel<<<128, 256, smem_bytes>>>(sites1, sites2, bonds,
                                          b_eq, W_att, b_att,
                                          idx1, idx2, out);
}

// round 2
// speedup vs baseline: 1.0350x; 1.0350x over previous
#include <cuda_runtime.h>

// Problem constants
#define B_TOT  2
#define E_TOT  2048
#define N1_TOT 96
#define K_TOT  32
#define CIN    64
#define CB     32
#define COUT   64
#define F_TOT  160          // 2*CIN + CB
#define NPAIR  80           // F_TOT/2
#define WCNT   (F_TOT*COUT) // 10240
#define NEG_SLOPE 0.01f

// Wbar = mean_g W_eq[g], stored in PAIRED layout for LDS.128:
//   float index i = ip*128 + t*4 + slot,  t in [0,32), slot in [0,4)
//   holds Wbar[f=2*ip + (slot>>1)][o=2*t + (slot&1)]
// so lane t's ld.shared.v2.u64 at (ip*32+t)*16B yields
//   {W[2ip][2t],W[2ip][2t+1]} , {W[2ip+1][2t],W[2ip+1][2t+1]}
__device__ float g_Wp[WCNT];

// ---------------------------------------------------------------------------
// Prep: Wbar into paired layout + zero d_out (poisoned by harness).
// ---------------------------------------------------------------------------
__global__ void prep_kernel(const float* __restrict__ W_eq, float* __restrict__ out) {
    int i = blockIdx.x * blockDim.x + threadIdx.x;
    if (i < WCNT) {
        const int ip = i >> 7, r = i & 127, t = r >> 2, slot = r & 3;
        const int f = 2 * ip + (slot >> 1);
        const int o = 2 * t + (slot & 1);
        const int idx = f * COUT + o;
        float s = W_eq[idx] + W_eq[WCNT + idx] + W_eq[2 * WCNT + idx] + W_eq[3 * WCNT + idx];
        g_Wp[i] = 0.25f * s;
    }
    if (i < B_TOT * K_TOT * COUT) out[i] = 0.0f;
}

// ---------------------------------------------------------------------------
// Main: per edge-instance (b,e):
//   v(160) = [sites1[b,idx1[e]], sites2[b,idx2[e]], bonds[b,e]]
//   lat    = leaky_relu(v @ Wbar + b_eq)
//   att    = sigmoid(lat . W_att + b_att)
//   atomicAdd(out[b, idx2[e], :], att * lat)
//
// 256 blocks x 128 threads (4 warps), 2 CTAs/SM. Each warp: 4 edges.
// Thread t owns output pair {2t, 2t+1}; fma.rn.f32x2; all inner-loop
// shared traffic via LDS.128.
// ---------------------------------------------------------------------------
__global__ void __launch_bounds__(128, 2) main_kernel(
    const float* __restrict__ sites1,
    const float* __restrict__ sites2,
    const float* __restrict__ bonds,
    const float* __restrict__ b_eq,
    const float* __restrict__ W_att,
    const float* __restrict__ b_att,
    const int*   __restrict__ idx1,
    const int*   __restrict__ idx2,
    float* __restrict__ out)
{
    extern __shared__ float smem[];
    float* Wsh = smem;                                              // 10240 f (40960 B)
    unsigned long long* vsh =
        (unsigned long long*)(smem + WCNT);                         // 4 warps * 4 edges * 160 u64 (20480 B)

    const int tid  = threadIdx.x;
    const int lane = tid & 31;
    const int w    = tid >> 5;

    // Stage Wbar (already paired) — straight float4 copy, L2-resident.
    {
        const float4* src = (const float4*)g_Wp;
        float4*       dst = (float4*)Wsh;
        #pragma unroll
        for (int i = 0; i < 20; i++) dst[i * 128 + tid] = src[i * 128 + tid];
    }

    // Gather v for this warp's 4 edges, duplicated into both f32x2 halves.
    const int ebase = blockIdx.x * 16 + w * 4;
    int bb[4], k2[4];
    unsigned long long* vw = vsh + (size_t)w * 4 * F_TOT;

    #pragma unroll
    for (int j = 0; j < 4; j++) {
        const int ei = ebase + j;            // 0..4095
        const int b  = ei >> 11;
        const int e  = ei & (E_TOT - 1);
        bb[j] = b;
        const int i1 = idx1[e];
        const int i2 = idx2[e];
        k2[j] = i2;
        #pragma unroll
        for (int m = 0; m < 5; m++) {
            const int f = lane + 32 * m;     // 0..159
            float v;
            if (f < CIN)            v = sites1[(b * N1_TOT + i1) * CIN + f];
            else if (f < 2 * CIN)   v = sites2[(b * K_TOT  + i2) * CIN + (f - CIN)];
            else                    v = bonds [(b * E_TOT  + e ) * CB  + (f - 2 * CIN)];
            const unsigned u = __float_as_uint(v);
            vw[j * F_TOT + f] = ((unsigned long long)u << 32) | (unsigned long long)u;
        }
    }
    __syncthreads();

    // Inner loop: 80 pair-iterations, all LDS.128.
    const ulonglong2* Wq = (const ulonglong2*)Wsh;
    const ulonglong2* v0 = (const ulonglong2*)(vw + 0 * F_TOT);
    const ulonglong2* v1 = (const ulonglong2*)(vw + 1 * F_TOT);
    const ulonglong2* v2 = (const ulonglong2*)(vw + 2 * F_TOT);
    const ulonglong2* v3 = (const ulonglong2*)(vw + 3 * F_TOT);

    unsigned long long a0 = 0ull, a1 = 0ull, a2 = 0ull, a3 = 0ull;

    #pragma unroll 10
    for (int ip = 0; ip < NPAIR; ip++) {
        const ulonglong2 wq = Wq[ip * 32 + lane];   // {W[2ip][2t..],W[2ip+1][2t..]}
        const ulonglong2 q0 = v0[ip];               // {v[2ip]x2, v[2ip+1]x2}
        const ulonglong2 q1 = v1[ip];
        const ulonglong2 q2 = v2[ip];
        const ulonglong2 q3 = v3[ip];
        asm("fma.rn.f32x2 %0, %1, %2, %0;" : "+l"(a0) : "l"(q0.x), "l"(wq.x));
        asm("fma.rn.f32x2 %0, %1, %2, %0;" : "+l"(a1) : "l"(q1.x), "l"(wq.x));
        asm("fma.rn.f32x2 %0, %1, %2, %0;" : "+l"(a2) : "l"(q2.x), "l"(wq.x));
        asm("fma.rn.f32x2 %0, %1, %2, %0;" : "+l"(a3) : "l"(q3.x), "l"(wq.x));
        asm("fma.rn.f32x2 %0, %1, %2, %0;" : "+l"(a0) : "l"(q0.y), "l"(wq.y));
        asm("fma.rn.f32x2 %0, %1, %2, %0;" : "+l"(a1) : "l"(q1.y), "l"(wq.y));
        asm("fma.rn.f32x2 %0, %1, %2, %0;" : "+l"(a2) : "l"(q2.y), "l"(wq.y));
        asm("fma.rn.f32x2 %0, %1, %2, %0;" : "+l"(a3) : "l"(q3.y), "l"(wq.y));
    }

    // Epilogue: bias, leaky-relu, attention (warp-reduced), sigmoid, scatter.
    const float be0 = b_eq[2 * lane];
    const float be1 = b_eq[2 * lane + 1];
    const float wa0 = W_att[2 * lane];
    const float wa1 = W_att[2 * lane + 1];
    const float ba  = b_att[0];

    unsigned long long accs[4] = {a0, a1, a2, a3};

    #pragma unroll
    for (int j = 0; j < 4; j++) {
        float y0 = __uint_as_float((unsigned)(accs[j] & 0xffffffffull));
        float y1 = __uint_as_float((unsigned)(accs[j] >> 32));
        y0 += be0; y1 += be1;
        y0 = (y0 > 0.0f) ? y0 : NEG_SLOPE * y0;
        y1 = (y1 > 0.0f) ? y1 : NEG_SLOPE * y1;

        float p = y0 * wa0 + y1 * wa1;
        #pragma unroll
        for (int s = 16; s > 0; s >>= 1)
            p += __shfl_xor_sync(0xffffffffu, p, s);
        const float att = 1.0f / (1.0f + __expf(-(p + ba)));

        float* dst = out + ((size_t)(bb[j] * K_TOT + k2[j])) * COUT + 2 * lane;
        atomicAdd(dst,     y0 * att);
        atomicAdd(dst + 1, y1 * att);
    }
}

// ---------------------------------------------------------------------------
extern "C" void kernel_launch(void* const* d_in, const int* in_sizes, int n_in,
                              void* d_out, int out_size)
{
    const float* sites1 = (const float*)d_in[0];
    const float* sites2 = (const float*)d_in[1];
    const float* bonds  = (const float*)d_in[2];
    const float* W_eq   = (const float*)d_in[3];
    const float* b_eq   = (const float*)d_in[4];
    const float* W_att  = (const float*)d_in[5];
    const float* b_att  = (const float*)d_in[6];
    // d_in[7] = idx2_oh (unused — collapsed analytically)
    const int*   idx1   = (const int*)d_in[8];
    const int*   idx2   = (const int*)d_in[9];
    // d_in[10], d_in[11] = perms1/perms2 (unused — permutations cancel)
    float* out = (float*)d_out;

    const int smem_bytes = WCNT * 4                    // Wsh  (40960)
                         + 4 * 4 * F_TOT * 8;          // vsh  (20480)
    cudaFuncSetAttribute(main_kernel,
                         cudaFuncAttributeMaxDynamicSharedMemorySize, smem_bytes);

    prep_kernel<<<40, 256>>>(W_eq, out);

    // 4096 edge instances / (4 warps * 4 edges) = 256 blocks
    main_kernel<<<256, 128, smem_bytes>>>(sites1, sites2, bonds,
                                          b_eq, W_att, b_att,
                                          idx1, idx2, out);
}

// round 3
// speedup vs baseline: 1.0376x; 1.0025x over previous
#include <cuda_runtime.h>

// Problem constants
#define B_TOT  2
#define E_TOT  2048
#define N1_TOT 96
#define K_TOT  32
#define CIN    64
#define CB     32
#define COUT   64
#define F_TOT  160          // 2*CIN + CB
#define NPAIR  80           // F_TOT/2
#define WCNT   (F_TOT*COUT) // 10240
#define NEG_SLOPE 0.01f

// Wbar = mean_g W_eq[g], PAIRED layout for LDS.128:
//   float index i = ip*128 + t*4 + slot  ->  Wbar[f=2*ip+(slot>>1)][o=2*t+(slot&1)]
// lane t's 16B load at (ip*32+t)*16 yields {W[2ip][2t],W[2ip][2t+1]},{W[2ip+1][2t],W[2ip+1][2t+1]}
__device__ float g_Wp[WCNT];

// ---------------------------------------------------------------------------
__global__ void prep_kernel(const float* __restrict__ W_eq, float* __restrict__ out) {
    int i = blockIdx.x * blockDim.x + threadIdx.x;
    if (i < WCNT) {
        const int ip = i >> 7, r = i & 127, t = r >> 2, slot = r & 3;
        const int f = 2 * ip + (slot >> 1);
        const int o = 2 * t + (slot & 1);
        const int idx = f * COUT + o;
        float s = W_eq[idx] + W_eq[WCNT + idx] + W_eq[2 * WCNT + idx] + W_eq[3 * WCNT + idx];
        g_Wp[i] = 0.25f * s;
    }
    if (i < B_TOT * K_TOT * COUT) out[i] = 0.0f;
}

// ---------------------------------------------------------------------------
// 256 CTAs x 256 threads (8 warps), 2 CTAs/SM. CTA owns 16 edges.
// Warp pair (h=0,1) x edge-group g: warp (h,g) accumulates edges 4g..4g+3
// over f-pairs ip = 2*i + h (i = 0..39). Partials combined via smem.
// Thread t owns output pair {2t, 2t+1}; fma.rn.f32x2 throughout.
// ---------------------------------------------------------------------------
__global__ void __launch_bounds__(256, 2) main_kernel(
    const float* __restrict__ sites1,
    const float* __restrict__ sites2,
    const float* __restrict__ bonds,
    const float* __restrict__ b_eq,
    const float* __restrict__ W_att,
    const float* __restrict__ b_att,
    const int*   __restrict__ idx1,
    const int*   __restrict__ idx2,
    float* __restrict__ out)
{
    extern __shared__ float smem[];
    float* Wsh = smem;                                       // 10240 f  (40960 B)
    unsigned long long* vsh  =
        (unsigned long long*)(smem + WCNT);                  // 16 edges * 160 u64 (20480 B)
    unsigned long long* psum = vsh + 16 * F_TOT;             // 512 u64 (4096 B)

    const int tid  = threadIdx.x;
    const int lane = tid & 31;
    const int w    = tid >> 5;
    const int h    = w >> 2;     // f-half: ip parity
    const int g    = w & 3;      // edge group

    // Stage Wbar (paired layout) — straight float4 copy, L2-resident.
    {
        const float4* src = (const float4*)g_Wp;
        float4*       dst = (float4*)Wsh;
        #pragma unroll
        for (int i = 0; i < 10; i++) dst[i * 256 + tid] = src[i * 256 + tid];
    }

    // Gather: each warp stages 2 of the CTA's 16 edges (dup into f32x2 halves).
    #pragma unroll
    for (int jj = 0; jj < 2; jj++) {
        const int j  = 2 * w + jj;                 // 0..15
        const int ei = blockIdx.x * 16 + j;        // 0..4095
        const int b  = ei >> 11;
        const int e  = ei & (E_TOT - 1);
        const int i1 = idx1[e];
        const int i2 = idx2[e];
        #pragma unroll
        for (int m = 0; m < 5; m++) {
            const int f = lane + 32 * m;           // 0..159
            float v;
            if (f < CIN)            v = sites1[(b * N1_TOT + i1) * CIN + f];
            else if (f < 2 * CIN)   v = sites2[(b * K_TOT  + i2) * CIN + (f - CIN)];
            else                    v = bonds [(b * E_TOT  + e ) * CB  + (f - 2 * CIN)];
            const unsigned u = __float_as_uint(v);
            vsh[j * F_TOT + f] = ((unsigned long long)u << 32) | (unsigned long long)u;
        }
    }
    __syncthreads();

    // Main loop: 40 f-pair iterations (ip = 2i + h), edges 4g..4g+3.
    const ulonglong2* Wq = (const ulonglong2*)Wsh;
    const ulonglong2* v0 = (const ulonglong2*)(vsh + (4 * g + 0) * F_TOT);
    const ulonglong2* v1 = (const ulonglong2*)(vsh + (4 * g + 1) * F_TOT);
    const ulonglong2* v2 = (const ulonglong2*)(vsh + (4 * g + 2) * F_TOT);
    const ulonglong2* v3 = (const ulonglong2*)(vsh + (4 * g + 3) * F_TOT);

    unsigned long long a0 = 0ull, a1 = 0ull, a2 = 0ull, a3 = 0ull;

    #pragma unroll 8
    for (int i = 0; i < 40; i++) {
        const int ip = 2 * i + h;
        const ulonglong2 wq = Wq[ip * 32 + lane];
        const ulonglong2 q0 = v0[ip];
        const ulonglong2 q1 = v1[ip];
        const ulonglong2 q2 = v2[ip];
        const ulonglong2 q3 = v3[ip];
        asm("fma.rn.f32x2 %0, %1, %2, %0;" : "+l"(a0) : "l"(q0.x), "l"(wq.x));
        asm("fma.rn.f32x2 %0, %1, %2, %0;" : "+l"(a1) : "l"(q1.x), "l"(wq.x));
        asm("fma.rn.f32x2 %0, %1, %2, %0;" : "+l"(a2) : "l"(q2.x), "l"(wq.x));
        asm("fma.rn.f32x2 %0, %1, %2, %0;" : "+l"(a3) : "l"(q3.x), "l"(wq.x));
        asm("fma.rn.f32x2 %0, %1, %2, %0;" : "+l"(a0) : "l"(q0.y), "l"(wq.y));
        asm("fma.rn.f32x2 %0, %1, %2, %0;" : "+l"(a1) : "l"(q1.y), "l"(wq.y));
        asm("fma.rn.f32x2 %0, %1, %2, %0;" : "+l"(a2) : "l"(q2.y), "l"(wq.y));
        asm("fma.rn.f32x2 %0, %1, %2, %0;" : "+l"(a3) : "l"(q3.y), "l"(wq.y));
    }

    // Combine partials: h=1 warps publish, h=0 warps reduce + epilogue.
    if (h == 1) {
        psum[(g * 4 + 0) * 32 + lane] = a0;
        psum[(g * 4 + 1) * 32 + lane] = a1;
        psum[(g * 4 + 2) * 32 + lane] = a2;
        psum[(g * 4 + 3) * 32 + lane] = a3;
    }
    __syncthreads();

    if (h == 0) {
        const float be0 = b_eq[2 * lane];
        const float be1 = b_eq[2 * lane + 1];
        const float wa0 = W_att[2 * lane];
        const float wa1 = W_att[2 * lane + 1];
        const float ba  = b_att[0];

        unsigned long long accs[4] = {a0, a1, a2, a3};

        #pragma unroll
        for (int jj = 0; jj < 4; jj++) {
            const unsigned long long pp = psum[(g * 4 + jj) * 32 + lane];
            float y0 = __uint_as_float((unsigned)(accs[jj] & 0xffffffffull))
                     + __uint_as_float((unsigned)(pp & 0xffffffffull));
            float y1 = __uint_as_float((unsigned)(accs[jj] >> 32))
                     + __uint_as_float((unsigned)(pp >> 32));
            y0 += be0; y1 += be1;
            y0 = (y0 > 0.0f) ? y0 : NEG_SLOPE * y0;
            y1 = (y1 > 0.0f) ? y1 : NEG_SLOPE * y1;

            float p = y0 * wa0 + y1 * wa1;
            #pragma unroll
            for (int s = 16; s > 0; s >>= 1)
                p += __shfl_xor_sync(0xffffffffu, p, s);
            const float att = 1.0f / (1.0f + __expf(-(p + ba)));

            const int ei = blockIdx.x * 16 + 4 * g + jj;
            const int b  = ei >> 11;
            const int e  = ei & (E_TOT - 1);
            const int k2 = idx2[e];

            float* dst = out + ((size_t)(b * K_TOT + k2)) * COUT + 2 * lane;
            atomicAdd(dst,     y0 * att);
            atomicAdd(dst + 1, y1 * att);
        }
    }
}

// ---------------------------------------------------------------------------
extern "C" void kernel_launch(void* const* d_in, const int* in_sizes, int n_in,
                              void* d_out, int out_size)
{
    const float* sites1 = (const float*)d_in[0];
    const float* sites2 = (const float*)d_in[1];
    const float* bonds  = (const float*)d_in[2];
    const float* W_eq   = (const float*)d_in[3];
    const float* b_eq   = (const float*)d_in[4];
    const float* W_att  = (const float*)d_in[5];
    const float* b_att  = (const float*)d_in[6];
    // d_in[7] = idx2_oh (unused — collapsed analytically)
    const int*   idx1   = (const int*)d_in[8];
    const int*   idx2   = (const int*)d_in[9];
    // d_in[10], d_in[11] = perms1/perms2 (unused — permutations cancel)
    float* out = (float*)d_out;

    const int smem_bytes = WCNT * 4                // Wsh   (40960)
                         + 16 * F_TOT * 8          // vsh   (20480)
                         + 512 * 8;                // psum  ( 4096)
    cudaFuncSetAttribute(main_kernel,
                         cudaFuncAttributeMaxDynamicSharedMemorySize, smem_bytes);

    prep_kernel<<<40, 256>>>(W_eq, out);

    // 4096 edges / 16 per CTA = 256 CTAs
    main_kernel<<<256, 256, smem_bytes>>>(sites1, sites2, bonds,
                                          b_eq, W_att, b_att,
                                          idx1, idx2, out);
}